// round 7
// baseline (speedup 1.0000x reference)
#include <cuda_runtime.h>

// out = e + (e @ B) @ A^T   with e:[16384,4096] f32, A,B:[4096,16] f32
// FUSED single kernel: out row m depends only on e row m.
// Block owns 32 rows. Phase 1: t_rows = e_rows @ B (B staged per 512-d chunk
// in SMEM, 4 rows/warp, t -> SMEM). Phase 2: out_rows = e_rows + t_rows @ A^T
// (e re-read hits L2: 296 resident blocks x 512KB = ~L2 capacity).

#define MROWS 16384
#define DDIM  4096
#define RANK  16
#define NCHUNK 8
#define CHUNKD (DDIM / NCHUNK)   // 512
#define ROWS_PER_BLK 32

// ---------------- packed f32x2 helpers ----------------
__device__ __forceinline__ unsigned long long pack2(float lo, float hi) {
    unsigned long long r;
    asm("mov.b64 %0, {%1, %2};" : "=l"(r) : "f"(lo), "f"(hi));
    return r;
}
__device__ __forceinline__ unsigned long long fma2(unsigned long long a,
                                                   unsigned long long b,
                                                   unsigned long long c) {
    unsigned long long d;
    asm("fma.rn.f32x2 %0, %1, %2, %3;" : "=l"(d) : "l"(a), "l"(b), "l"(c));
    return d;
}
__device__ __forceinline__ unsigned long long add2(unsigned long long a,
                                                   unsigned long long b) {
    unsigned long long d;
    asm("add.rn.f32x2 %0, %1, %2;" : "=l"(d) : "l"(a), "l"(b));
    return d;
}
__device__ __forceinline__ void unpack2(unsigned long long v, float& lo, float& hi) {
    asm("mov.b64 {%0, %1}, %2;" : "=f"(lo), "=f"(hi) : "l"(v));
}
__device__ __forceinline__ unsigned long long shfl_xor_u64(unsigned long long v, int m) {
    unsigned int lo = (unsigned int)(v & 0xffffffffull);
    unsigned int hi = (unsigned int)(v >> 32);
    lo = __shfl_xor_sync(0xffffffffu, lo, m);
    hi = __shfl_xor_sync(0xffffffffu, hi, m);
    return ((unsigned long long)hi << 32) | lo;
}

// ---------------- fused kernel ----------------
// 256 threads = 8 warps; grid = 512 blocks (32 rows each); occ 2.
__global__ __launch_bounds__(256, 2) void fused_lowrank(
    const float* __restrict__ e,
    const float* __restrict__ A,
    const float* __restrict__ B,
    float* __restrict__ out) {
    __shared__ __align__(16) unsigned long long Bs[8][CHUNKD];  // 32 KB
    __shared__ __align__(16) float t_s[ROWS_PER_BLK * RANK];    // 2 KB

    const int tid  = threadIdx.x;
    const int wid  = tid >> 5;
    const int lane = tid & 31;
    const int row0 = blockIdx.x * ROWS_PER_BLK;      // block's first row
    const int wrow = row0 + wid * 4;                 // warp's first row

    // ======================= Phase 1: t = e @ B =======================
    unsigned long long acc[4][8];
#pragma unroll
    for (int i = 0; i < 4; i++)
#pragma unroll
        for (int p = 0; p < 8; p++) acc[i][p] = 0ull;

    const float* erow = e + (size_t)wrow * DDIM;

    for (int chunk = 0; chunk < NCHUNK; chunk++) {
        const int dbase = chunk * CHUNKD;

        __syncthreads();  // protect Bs from previous chunk's readers
        {
            const float4* Bg =
                reinterpret_cast<const float4*>(B + (size_t)dbase * RANK);
#pragma unroll
            for (int it = 0; it < 8; it++) {
                int idx = it * 256 + tid;          // 0..2047
                int d = idx >> 2;                  // 0..511
                int q = idx & 3;
                float4 v = Bg[(size_t)d * 4 + q];  // coalesced LDG.128
                Bs[q * 2 + 0][d] = pack2(v.x, v.y);
                Bs[q * 2 + 1][d] = pack2(v.z, v.w);
            }
        }
        __syncthreads();

        const float* e0 = erow + dbase;

#pragma unroll 2
        for (int k = 0; k < CHUNKD / 32; k++) {
            const int d = k * 32 + lane;

            float ev0 = e0[0 * DDIM + d];
            float ev1 = e0[1 * DDIM + d];
            float ev2 = e0[2 * DDIM + d];
            float ev3 = e0[3 * DDIM + d];

            unsigned long long bp[8];
#pragma unroll
            for (int p = 0; p < 8; p++) bp[p] = Bs[p][d];  // conflict-free LDS.64

            unsigned long long e2[4] = { pack2(ev0, ev0), pack2(ev1, ev1),
                                         pack2(ev2, ev2), pack2(ev3, ev3) };
#pragma unroll
            for (int i = 0; i < 4; i++)
#pragma unroll
                for (int p = 0; p < 8; p++)
                    acc[i][p] = fma2(e2[i], bp[p], acc[i][p]);
        }
    }

    // butterfly reduce across lanes (once per warp)
#pragma unroll
    for (int off = 16; off > 0; off >>= 1) {
#pragma unroll
        for (int i = 0; i < 4; i++)
#pragma unroll
            for (int p = 0; p < 8; p++)
                acc[i][p] = add2(acc[i][p], shfl_xor_u64(acc[i][p], off));
    }

    if (lane < 8) {
        unsigned long long* tq = reinterpret_cast<unsigned long long*>(t_s);
#pragma unroll
        for (int i = 0; i < 4; i++)
            tq[(size_t)(wid * 4 + i) * 8 + lane] = acc[i][lane];
    }

    __syncthreads();  // t_s complete

    // =================== Phase 2: out = e + t @ A^T ===================
    // 8 passes over the 4096 columns; thread owns 2 cols per pass.
    // e re-read: this block's 512KB tile is L2-resident from phase 1.
#pragma unroll 1
    for (int pass = 0; pass < 8; pass++) {
        const int c0 = pass * 512 + tid * 2;

        // A rows for this pass's 2 columns (L2-hot; A totals 256KB)
        unsigned long long a2[2][8];
#pragma unroll
        for (int j = 0; j < 2; j++) {
            const ulonglong2* Aq =
                reinterpret_cast<const ulonglong2*>(A + (size_t)(c0 + j) * RANK);
            ulonglong2 v0 = Aq[0], v1 = Aq[1], v2 = Aq[2], v3 = Aq[3];
            a2[j][0] = v0.x; a2[j][1] = v0.y;
            a2[j][2] = v1.x; a2[j][3] = v1.y;
            a2[j][4] = v2.x; a2[j][5] = v2.y;
            a2[j][6] = v3.x; a2[j][7] = v3.y;
        }

        const float* ep = e + (size_t)row0 * DDIM + c0;
        float* op = out + (size_t)row0 * DDIM + c0;

#pragma unroll 1
        for (int m0 = 0; m0 < ROWS_PER_BLK; m0 += 4) {
            // batch 4 independent e loads (L2 hits) up front
            float2 ev[4];
#pragma unroll
            for (int i = 0; i < 4; i++)
                ev[i] = *reinterpret_cast<const float2*>(ep + (size_t)(m0 + i) * DDIM);

#pragma unroll
            for (int i = 0; i < 4; i++) {
                // t row: warp-uniform address -> LDS broadcast
                const ulonglong2* tq =
                    reinterpret_cast<const ulonglong2*>(t_s + (m0 + i) * RANK);
                ulonglong2 t01 = tq[0], t23 = tq[1], t45 = tq[2], t67 = tq[3];
                unsigned long long t2[8] = { t01.x, t01.y, t23.x, t23.y,
                                             t45.x, t45.y, t67.x, t67.y };
                float o[2];
#pragma unroll
                for (int j = 0; j < 2; j++) {
                    unsigned long long s = 0ull;
#pragma unroll
                    for (int p = 0; p < 8; p++) s = fma2(t2[p], a2[j][p], s);
                    float lo, hi;
                    unpack2(s, lo, hi);
                    o[j] = (j == 0 ? ev[i].x : ev[i].y) + (lo + hi);
                }
                *reinterpret_cast<float2*>(op + (size_t)(m0 + i) * DDIM) =
                    make_float2(o[0], o[1]);
            }
        }
    }
}

extern "C" void kernel_launch(void* const* d_in, const int* in_sizes, int n_in,
                              void* d_out, int out_size) {
    const float* e = (const float*)d_in[0];  // [4,4096,4096]
    const float* A = (const float*)d_in[1];  // [4096,16]
    const float* B = (const float*)d_in[2];  // [4096,16]
    float* out = (float*)d_out;

    (void)in_sizes; (void)n_in; (void)out_size;

    fused_lowrank<<<MROWS / ROWS_PER_BLK, 256>>>(e, A, B, out);
}

// round 8
// speedup vs baseline: 1.6445x; 1.6445x over previous
#include <cuda_runtime.h>
#include <cstdint>

// out = e + (e @ B) @ A^T   with e:[16384,4096] f32, A,B:[4096,16] f32
// Tensor-core path: both GEMMs via mma.sync.m16n8k16 (bf16 in, f32 accum).
// Correction term is ~2.6% of out, so bf16 products keep rel_err ~1e-4.
//
// k0:    pre-pack A and B into bf16 mma fragments (gmem, 256KB).
// fused: block = 32 rows. Phase 1: t-frags = e @ B (4-way k-split per row-tile,
//        reduced via smem, repacked as bf16 A-operand frags in smem).
//        Phase 2: out = mma(t_frag, A_frag, C=e)  — the +e rides in the
//        accumulator init; 1 mma per 16x8 output tile.

#define MROWS 16384
#define DDIM  4096
#define RANK  16

// B fragments: [kstep(256)][ntile(2)][lane(32)] packed u64 {b0b1, b2b3}
__device__ __align__(16) unsigned long long g_Bfrag[512 * 32];
// A fragments: [col_tile(512)][lane(32)] packed u64
__device__ __align__(16) unsigned long long g_Afrag[512 * 32];

// pack two f32 -> bf16x2 (lo in low 16 bits)
__device__ __forceinline__ uint32_t pk_bf16(float lo, float hi) {
    uint32_t r;
    asm("cvt.rn.bf16x2.f32 %0, %1, %2;" : "=r"(r) : "f"(hi), "f"(lo));
    return r;
}

// D += A(16x16 bf16, row) * B(16x8 bf16, col), f32 accum (in-place)
__device__ __forceinline__ void mma_bf16(
    float& d0, float& d1, float& d2, float& d3,
    uint32_t a0, uint32_t a1, uint32_t a2, uint32_t a3,
    uint32_t b0, uint32_t b1) {
    asm("mma.sync.aligned.m16n8k16.row.col.f32.bf16.bf16.f32 "
        "{%0,%1,%2,%3},{%4,%5,%6,%7},{%8,%9},{%0,%1,%2,%3};"
        : "+f"(d0), "+f"(d1), "+f"(d2), "+f"(d3)
        : "r"(a0), "r"(a1), "r"(a2), "r"(a3), "r"(b0), "r"(b1));
}

// ---------------- k0: build bf16 fragments for A and B ----------------
// 32768 threads. First 16384: B frags (512 jobs x 32 lanes).
// Next 16384: A frags (512 col-tiles x 32 lanes).
__global__ __launch_bounds__(256) void k0_frags(const float* __restrict__ A,
                                                const float* __restrict__ B) {
    int t = blockIdx.x * 256 + threadIdx.x;
    int lane = t & 31;
    int g = lane >> 2, tg = lane & 3;
    if (t < 16384) {
        int job = t >> 5;             // kstep*2 + ntile
        int kstep = job >> 1, nt = job & 1;
        int k = kstep * 16;
        int c = nt * 8 + g;           // rank index
        // B-operand frag: b0,b1 = B[k+tg*2 / +1][c]; b2,b3 = rows +8,+9
        uint32_t lo = pk_bf16(B[(k + tg * 2) * RANK + c],
                              B[(k + tg * 2 + 1) * RANK + c]);
        uint32_t hi = pk_bf16(B[(k + tg * 2 + 8) * RANK + c],
                              B[(k + tg * 2 + 9) * RANK + c]);
        g_Bfrag[(size_t)job * 32 + lane] =
            ((unsigned long long)hi << 32) | lo;
    } else {
        int job = (t - 16384) >> 5;   // col tile ct
        int c = job * 8 + g;          // output column
        // B-operand frag for phase 2: Bop[k=r][n=c] = A[c][r]
        uint32_t lo = pk_bf16(A[(size_t)c * RANK + tg * 2],
                              A[(size_t)c * RANK + tg * 2 + 1]);
        uint32_t hi = pk_bf16(A[(size_t)c * RANK + tg * 2 + 8],
                              A[(size_t)c * RANK + tg * 2 + 9]);
        g_Afrag[(size_t)job * 32 + lane] =
            ((unsigned long long)hi << 32) | lo;
    }
}

// ---------------- fused main kernel ----------------
// grid 512, block 256 (8 warps). Block owns 32 rows (2 row-tiles of 16).
// Phase 1: warp (rt = wid>>2, q = wid&3) does ksteps [q*64, q*64+64).
// Phase 2: warp (rt = wid&1, cq = wid>>1) does col-tiles [cq*128, +128).
__global__ __launch_bounds__(256) void fused_mma(const float* __restrict__ e,
                                                 float* __restrict__ out) {
    __shared__ float sacc[8][32][8];    // 8 KB: per-warp partial accum
    __shared__ uint4 stfrag[2][32];     // 1 KB: t as bf16 A-operand frags

    const int tid  = threadIdx.x;
    const int wid  = tid >> 5;
    const int lane = tid & 31;
    const int g    = lane >> 2;   // groupID (row within tile)
    const int tg   = lane & 3;    // thread-in-group (col pair)
    const int blkrow = blockIdx.x * 32;

    // ======================= Phase 1: t = e @ B =======================
    {
        const int rt = wid >> 2;       // row-tile 0/1
        const int q  = wid & 3;        // k quadrant
        const int r0 = blkrow + rt * 16;

        float tA0 = 0.f, tA1 = 0.f, tA2 = 0.f, tA3 = 0.f;  // ranks 0-7
        float tB0 = 0.f, tB1 = 0.f, tB2 = 0.f, tB3 = 0.f;  // ranks 8-15

        const float* erow = e + (size_t)(r0 + g) * DDIM + tg * 2;
        const unsigned long long* bf =
            g_Bfrag + (size_t)(q * 64) * 2 * 32 + lane;

#pragma unroll 2
        for (int ks = 0; ks < 64; ks++) {
            const float* ek = erow + (q * 64 + ks) * 16;
            float2 f0 = *reinterpret_cast<const float2*>(ek);
            float2 f1 = *reinterpret_cast<const float2*>(ek + 8 * DDIM);
            float2 f2 = *reinterpret_cast<const float2*>(ek + 8);
            float2 f3 = *reinterpret_cast<const float2*>(ek + 8 * DDIM + 8);
            unsigned long long b0 = bf[(size_t)ks * 64];        // ntile 0
            unsigned long long b1 = bf[(size_t)ks * 64 + 32];   // ntile 1

            uint32_t a0 = pk_bf16(f0.x, f0.y);
            uint32_t a1 = pk_bf16(f1.x, f1.y);
            uint32_t a2 = pk_bf16(f2.x, f2.y);
            uint32_t a3 = pk_bf16(f3.x, f3.y);

            mma_bf16(tA0, tA1, tA2, tA3, a0, a1, a2, a3,
                     (uint32_t)b0, (uint32_t)(b0 >> 32));
            mma_bf16(tB0, tB1, tB2, tB3, a0, a1, a2, a3,
                     (uint32_t)b1, (uint32_t)(b1 >> 32));
        }

        // stage partials
        float* s = sacc[wid][lane];
        s[0] = tA0; s[1] = tA1; s[2] = tA2; s[3] = tA3;
        s[4] = tB0; s[5] = tB1; s[6] = tB2; s[7] = tB3;
    }
    __syncthreads();

    // reduce 4 k-quadrants and pack t as bf16 A-operand frags
    if (tid < 64) {
        const int rt = tid >> 5;
        const int ln = tid & 31;
        float s[8];
#pragma unroll
        for (int j = 0; j < 8; j++)
            s[j] = sacc[rt * 4 + 0][ln][j] + sacc[rt * 4 + 1][ln][j] +
                   sacc[rt * 4 + 2][ln][j] + sacc[rt * 4 + 3][ln][j];
        // D-frag -> A-frag mapping is identity per (lane):
        // areg0 = t[g][tg*2,+1], areg1 = t[g+8][..], areg2/3 = cols +8/+9
        stfrag[rt][ln] = make_uint4(pk_bf16(s[0], s[1]), pk_bf16(s[2], s[3]),
                                    pk_bf16(s[4], s[5]), pk_bf16(s[6], s[7]));
    }
    __syncthreads();

    // =================== Phase 2: out = e + t @ A^T ===================
    {
        const int rt = wid & 1;
        const int cq = wid >> 1;       // col quarter (128 col-tiles of 8)
        const int r0 = blkrow + rt * 16;

        const uint4 tf = stfrag[rt][lane];

        const float* ebase = e + (size_t)(r0 + g) * DDIM + tg * 2;
        float* obase = out + (size_t)(r0 + g) * DDIM + tg * 2;
        const unsigned long long* afp =
            g_Afrag + (size_t)(cq * 128) * 32 + lane;

#pragma unroll 4
        for (int ctl = 0; ctl < 128; ctl++) {
            unsigned long long af = afp[(size_t)ctl * 32];
            const int coff = (cq * 128 + ctl) * 8;

            // load e straight into the mma accumulator (the "+ e")
            float2 e0 = *reinterpret_cast<const float2*>(ebase + coff);
            float2 e1 = *reinterpret_cast<const float2*>(ebase + 8 * DDIM + coff);
            float d0 = e0.x, d1 = e0.y, d2 = e1.x, d3 = e1.y;

            mma_bf16(d0, d1, d2, d3, tf.x, tf.y, tf.z, tf.w,
                     (uint32_t)af, (uint32_t)(af >> 32));

            *reinterpret_cast<float2*>(obase + coff) = make_float2(d0, d1);
            *reinterpret_cast<float2*>(obase + 8 * DDIM + coff) =
                make_float2(d2, d3);
        }
    }
}

extern "C" void kernel_launch(void* const* d_in, const int* in_sizes, int n_in,
                              void* d_out, int out_size) {
    const float* e = (const float*)d_in[0];  // [4,4096,4096]
    const float* A = (const float*)d_in[1];  // [4096,16]
    const float* B = (const float*)d_in[2];  // [4096,16]
    float* out = (float*)d_out;

    (void)in_sizes; (void)n_in; (void)out_size;

    k0_frags<<<128, 256>>>(A, B);
    fused_mma<<<MROWS / 32, 256>>>(e, out);
}

// round 11
// speedup vs baseline: 1.7934x; 1.0906x over previous
#include <cuda_runtime.h>
#include <cstdint>

// out = e + (e @ B) @ A^T   with e:[16384,4096] f32, A,B:[4096,16] f32
// Tensor-core path (m16n8k16 bf16, f32 accum) with PERMUTED k and n mappings
// chosen so every per-lane e access is a contiguous float4:
//  - phase 1: k-permutation sigma puts the lane's 4 k-elements at d=4tg..4tg+3
//  - phase 2: paired n-tiles with col = 4*(n>>1) + 2*tile + (n&1) put the
//    lane's 4 output cols at 4tg..4tg+3  -> float4 loads AND stores.
// k0 pre-packs A,B fragments honoring these permutations (gmem, 256KB).

#define MROWS 16384
#define DDIM  4096
#define RANK  16

// Phase-1 B fragments: [kstep(256)][lane(32)] = {ntile0 u64, ntile1 u64}
__device__ __align__(16) ulonglong2 g_Bfrag2[256 * 32];
// Phase-2 A fragments: [ct2(256)][lane(32)] = {t0lo, t0hi, t1lo, t1hi}
__device__ __align__(16) uint4 g_Afrag2[256 * 32];

// pack two f32 -> bf16x2 (lo in low 16 bits)
__device__ __forceinline__ uint32_t pk_bf16(float lo, float hi) {
    uint32_t r;
    asm("cvt.rn.bf16x2.f32 %0, %1, %2;" : "=r"(r) : "f"(hi), "f"(lo));
    return r;
}

// D += A(16x16 bf16, row) * B(16x8 bf16, col), f32 accum (in-place)
__device__ __forceinline__ void mma_bf16(
    float& d0, float& d1, float& d2, float& d3,
    uint32_t a0, uint32_t a1, uint32_t a2, uint32_t a3,
    uint32_t b0, uint32_t b1) {
    asm("mma.sync.aligned.m16n8k16.row.col.f32.bf16.bf16.f32 "
        "{%0,%1,%2,%3},{%4,%5,%6,%7},{%8,%9},{%0,%1,%2,%3};"
        : "+f"(d0), "+f"(d1), "+f"(d2), "+f"(d3)
        : "r"(a0), "r"(a1), "r"(a2), "r"(a3), "r"(b0), "r"(b1));
}

// ---------------- k0: build bf16 fragments for A and B ----------------
// 32768 threads. First 16384: B frags (kstep 256 x nt 2 x 32 lanes).
// Next 16384: A frags (ct2 256 x tile 2 x 32 lanes).
__global__ __launch_bounds__(256) void k0_frags(const float* __restrict__ A,
                                                const float* __restrict__ B) {
    int t = blockIdx.x * 256 + threadIdx.x;
    int lane = t & 31;
    int g = lane >> 2, tg = lane & 3;
    if (t < 16384) {
        int job = t >> 5;
        int kstep = job >> 1, nt = job & 1;
        int k = kstep * 16;
        int c = nt * 8 + g;                 // rank index (n of phase-1 mma)
        // k-permutation sigma: frag k {2tg,2tg+1,2tg+8,2tg+9} -> global
        // d = k + {4tg, 4tg+1, 4tg+2, 4tg+3}
        uint32_t lo = pk_bf16(B[(k + 4 * tg + 0) * RANK + c],
                              B[(k + 4 * tg + 1) * RANK + c]);
        uint32_t hi = pk_bf16(B[(k + 4 * tg + 2) * RANK + c],
                              B[(k + 4 * tg + 3) * RANK + c]);
        reinterpret_cast<unsigned long long*>(g_Bfrag2)
            [(size_t)(kstep * 32 + lane) * 2 + nt] =
            ((unsigned long long)hi << 32) | lo;
    } else {
        int job = (t - 16384) >> 5;
        int ct2 = job >> 1, tile = job & 1;
        // n-permutation over paired tiles: global col for n-index g
        int c = ct2 * 16 + 4 * (g >> 1) + 2 * tile + (g & 1);
        // phase-2 k (rank) mapping is identity
        uint32_t lo = pk_bf16(A[(size_t)c * RANK + 2 * tg],
                              A[(size_t)c * RANK + 2 * tg + 1]);
        uint32_t hi = pk_bf16(A[(size_t)c * RANK + 2 * tg + 8],
                              A[(size_t)c * RANK + 2 * tg + 9]);
        reinterpret_cast<unsigned long long*>(g_Afrag2)
            [(size_t)(ct2 * 32 + lane) * 2 + tile] =
            ((unsigned long long)hi << 32) | lo;
    }
}

// ---------------- fused main kernel ----------------
// grid 512, block 256 (8 warps). Block owns 32 rows (2 row-tiles of 16).
// Phase 1: warp (rt = wid>>2, q = wid&3) does ksteps [q*64, q*64+64).
// Phase 2: warp (rt = wid&1, cq = wid>>1) does double-tiles [cq*64, +64).
__global__ __launch_bounds__(256) void fused_mma(const float* __restrict__ e,
                                                 float* __restrict__ out) {
    __shared__ float sacc[8][32][8];    // 8 KB: per-warp partial accum
    __shared__ uint4 stfrag[2][32];     // 1 KB: t as bf16 A-operand frags

    const int tid  = threadIdx.x;
    const int wid  = tid >> 5;
    const int lane = tid & 31;
    const int g    = lane >> 2;   // groupID (row within tile)
    const int tg   = lane & 3;    // thread-in-group
    const int blkrow = blockIdx.x * 32;

    // ======================= Phase 1: t = e @ B =======================
    {
        const int rt = wid >> 2;       // row-tile 0/1
        const int q  = wid & 3;        // k quadrant
        const int r0 = blkrow + rt * 16;

        float tA0 = 0.f, tA1 = 0.f, tA2 = 0.f, tA3 = 0.f;  // ranks 0-7
        float tB0 = 0.f, tB1 = 0.f, tB2 = 0.f, tB3 = 0.f;  // ranks 8-15

        const float* erow = e + (size_t)(r0 + g) * DDIM + tg * 4;
        const ulonglong2* bf = g_Bfrag2 + (size_t)(q * 64) * 32 + lane;

#pragma unroll 2
        for (int ks = 0; ks < 64; ks++) {
            const float* ek = erow + (q * 64 + ks) * 16;
            float4 f0 = *reinterpret_cast<const float4*>(ek);            // row g
            float4 f1 = *reinterpret_cast<const float4*>(ek + 8 * DDIM); // row g+8
            ulonglong2 b = bf[(size_t)ks * 32];

            // sigma mapping: (x,y) -> frag k 2tg,2tg+1 ; (z,w) -> 2tg+8,2tg+9
            uint32_t a0 = pk_bf16(f0.x, f0.y);
            uint32_t a2 = pk_bf16(f0.z, f0.w);
            uint32_t a1 = pk_bf16(f1.x, f1.y);
            uint32_t a3 = pk_bf16(f1.z, f1.w);

            mma_bf16(tA0, tA1, tA2, tA3, a0, a1, a2, a3,
                     (uint32_t)b.x, (uint32_t)(b.x >> 32));
            mma_bf16(tB0, tB1, tB2, tB3, a0, a1, a2, a3,
                     (uint32_t)b.y, (uint32_t)(b.y >> 32));
        }

        float* s = sacc[wid][lane];
        s[0] = tA0; s[1] = tA1; s[2] = tA2; s[3] = tA3;
        s[4] = tB0; s[5] = tB1; s[6] = tB2; s[7] = tB3;
    }
    __syncthreads();

    // reduce 4 k-quadrants and pack t as bf16 A-operand frags (identity k)
    if (tid < 64) {
        const int rt = tid >> 5;
        const int ln = tid & 31;
        float s[8];
#pragma unroll
        for (int j = 0; j < 8; j++)
            s[j] = sacc[rt * 4 + 0][ln][j] + sacc[rt * 4 + 1][ln][j] +
                   sacc[rt * 4 + 2][ln][j] + sacc[rt * 4 + 3][ln][j];
        stfrag[rt][ln] = make_uint4(pk_bf16(s[0], s[1]), pk_bf16(s[2], s[3]),
                                    pk_bf16(s[4], s[5]), pk_bf16(s[6], s[7]));
    }
    __syncthreads();

    // =================== Phase 2: out = e + t @ A^T ===================
    {
        const int rt = wid & 1;
        const int cq = wid >> 1;       // col quarter: 64 double-tiles of 16
        const int r0 = blkrow + rt * 16;

        const uint4 tf = stfrag[rt][lane];

        const float* ebase = e + (size_t)(r0 + g) * DDIM + tg * 4;
        float* obase = out + (size_t)(r0 + g) * DDIM + tg * 4;
        const uint4* afp = g_Afrag2 + (size_t)(cq * 64) * 32 + lane;

#pragma unroll 4
        for (int ct = 0; ct < 64; ct++) {
            uint4 af = afp[(size_t)ct * 32];
            const int coff = (cq * 64 + ct) * 16;

            // e rides in the accumulators; lane covers 4 contiguous cols
            float4 e0 = *reinterpret_cast<const float4*>(ebase + coff);
            float4 e1 = *reinterpret_cast<const float4*>(ebase + 8 * DDIM + coff);

            float d0 = e0.x, d1 = e0.y, d2 = e1.x, d3 = e1.y;   // tile0
            float q0 = e0.z, q1 = e0.w, q2 = e1.z, q3 = e1.w;   // tile1

            mma_bf16(d0, d1, d2, d3, tf.x, tf.y, tf.z, tf.w, af.x, af.y);
            mma_bf16(q0, q1, q2, q3, tf.x, tf.y, tf.z, tf.w, af.z, af.w);

            *reinterpret_cast<float4*>(obase + coff) =
                make_float4(d0, d1, q0, q1);
            *reinterpret_cast<float4*>(obase + 8 * DDIM + coff) =
                make_float4(d2, d3, q2, q3);
        }
    }
}

extern "C" void kernel_launch(void* const* d_in, const int* in_sizes, int n_in,
                              void* d_out, int out_size) {
    const float* e = (const float*)d_in[0];  // [4,4096,4096]
    const float* A = (const float*)d_in[1];  // [4096,16]
    const float* B = (const float*)d_in[2];  // [4096,16]
    float* out = (float*)d_out;

    (void)in_sizes; (void)n_in; (void)out_size;

    k0_frags<<<128, 256>>>(A, B);
    fused_mma<<<MROWS / 32, 256>>>(e, out);
}